// round 1
// baseline (speedup 1.0000x reference)
#include <cuda_runtime.h>
#include <cstdint>

#define Nn   3072
#define FIN  512
#define FH   64
#define NH   8
#define CC   512     // NH*FH
#define NC   16
#define LRA  0.2f
#define JSPLIT 3
#define JCHUNK 1024  // Nn/JSPLIT
#define TI   64
#define TJ   32
#define KS   545     // p_s k-stride (odd -> conflict-free)
#define TI5  8

// ---- static device scratch (no allocations allowed) ----
__device__ float g_Wh[Nn * CC];          // [n][h*64+o]
__device__ float g_srcT[Nn * NH];        // [n][h]
__device__ float g_dstT[Nn * NH];        // [n][h]
__device__ float g_Zinv[Nn * NH];        // [n][h]
__device__ float g_hp[JSPLIT][Nn * CC];  // partial h' per j-split
__device__ float g_Wh2[Nn * NC];
__device__ float g_s2[Nn];
__device__ float g_d2[Nn];

__device__ __forceinline__ float lrelu(float x) { return fmaxf(x, LRA * x); }

// ================= K1: Wh = x @ W (64x64 tile SGEMM) =================
__global__ void __launch_bounds__(256) k1_gemm(const float* __restrict__ x,
                                               const float* __restrict__ W) {
    __shared__ float As[16][64];   // [k][row]
    __shared__ float Bs[16][64];   // [k][col]
    int tx = threadIdx.x & 15, ty = threadIdx.x >> 4;
    int row0 = blockIdx.y * 64, col0 = blockIdx.x * 64;
    int h = col0 >> 6;                         // 64-wide col tile = one head
    const float* Wb = W + (size_t)h * FIN * FH; // [FIN][64]
    float acc[4][4];
#pragma unroll
    for (int i = 0; i < 4; i++)
#pragma unroll
        for (int j = 0; j < 4; j++) acc[i][j] = 0.f;

    for (int k0 = 0; k0 < FIN; k0 += 16) {
        {
            int t = threadIdx.x;
            int r = t >> 2;
            int c4 = (t & 3) << 2;
            float4 v = *(const float4*)&x[(size_t)(row0 + r) * FIN + k0 + c4];
            As[c4 + 0][r] = v.x; As[c4 + 1][r] = v.y;
            As[c4 + 2][r] = v.z; As[c4 + 3][r] = v.w;
        }
        {
            int t = threadIdx.x;
            int r = t >> 4;
            int c4 = (t & 15) << 2;
            float4 v = *(const float4*)&Wb[(size_t)(k0 + r) * FH + c4];
            *(float4*)&Bs[r][c4] = v;
        }
        __syncthreads();
#pragma unroll
        for (int k = 0; k < 16; k++) {
            float4 a4 = *(const float4*)&As[k][ty * 4];
            float4 b4 = *(const float4*)&Bs[k][tx * 4];
            float a[4] = {a4.x, a4.y, a4.z, a4.w};
            float b[4] = {b4.x, b4.y, b4.z, b4.w};
#pragma unroll
            for (int i = 0; i < 4; i++)
#pragma unroll
                for (int j = 0; j < 4; j++) acc[i][j] += a[i] * b[j];
        }
        __syncthreads();
    }
#pragma unroll
    for (int i = 0; i < 4; i++) {
        float4 v = make_float4(acc[i][0], acc[i][1], acc[i][2], acc[i][3]);
        *(float4*)&g_Wh[(size_t)(row0 + ty * 4 + i) * CC + col0 + tx * 4] = v;
    }
}

// ================= K1b: src/dst projections =================
__global__ void __launch_bounds__(256) k_srcdst(const float* __restrict__ a_src,
                                                const float* __restrict__ a_dst) {
    int n = blockIdx.x;
    int h = threadIdx.x >> 5, lane = threadIdx.x & 31;
    const float* wh = g_Wh + (size_t)n * CC + h * FH;
    float w0 = wh[lane], w1 = wh[lane + 32];
    float s = w0 * a_src[h * FH + lane] + w1 * a_src[h * FH + lane + 32];
    float d = w0 * a_dst[h * FH + lane] + w1 * a_dst[h * FH + lane + 32];
#pragma unroll
    for (int o = 16; o; o >>= 1) {
        s += __shfl_down_sync(0xffffffffu, s, o);
        d += __shfl_down_sync(0xffffffffu, d, o);
    }
    if (!lane) { g_srcT[n * NH + h] = s; g_dstT[n * NH + h] = d; }
}

// ================= K2: softmax denominators Z[h,i] =================
__global__ void __launch_bounds__(256) k2_z(const int* __restrict__ adj) {
    int i = blockIdx.x;
    float sr[NH], sum[NH];
#pragma unroll
    for (int h = 0; h < NH; h++) { sr[h] = g_srcT[i * NH + h]; sum[h] = 0.f; }
    const int* arow = adj + (size_t)i * Nn;
    for (int j = threadIdx.x; j < Nn; j += 256) {
        if (arow[j] > 0) {
            const float4* dp = (const float4*)(g_dstT + (size_t)j * NH);
            float4 d0 = dp[0], d1 = dp[1];
            float dv[8] = {d0.x, d0.y, d0.z, d0.w, d1.x, d1.y, d1.z, d1.w};
#pragma unroll
            for (int h = 0; h < NH; h++) sum[h] += __expf(lrelu(sr[h] + dv[h]));
        }
    }
    __shared__ float red[8][NH];
    int lane = threadIdx.x & 31, w = threadIdx.x >> 5;
#pragma unroll
    for (int h = 0; h < NH; h++) {
        float v = sum[h];
#pragma unroll
        for (int o = 16; o; o >>= 1) v += __shfl_down_sync(0xffffffffu, v, o);
        if (!lane) red[w][h] = v;
    }
    __syncthreads();
    if (threadIdx.x < NH) {
        float v = 0.f;
#pragma unroll
        for (int ww = 0; ww < 8; ww++) v += red[ww][threadIdx.x];
        g_Zinv[i * NH + threadIdx.x] = 1.f / v;
    }
}

// ====== K3: fused attention p-gen + avg_attention write + (att @ Wh) ======
__global__ void __launch_bounds__(512) k3_att(const int* __restrict__ adj,
                                              float* __restrict__ avg) {
    extern __shared__ float sm[];
    float* wh_s   = sm;                       // TJ*CC   = 16384
    float* p_s    = sm + TJ * CC;             // TJ*KS   = 17440
    float* dst_s  = p_s + TJ * KS;            // NH*TJ   = 256   [h][k]
    float* zinv_s = dst_s + NH * TJ;          // TI*NH   = 512   [r][h]
    float* src_s  = zinv_s + TI * NH;         // TI*NH   = 512

    int t = threadIdx.x;
    int i0 = blockIdx.y * TI;
    int jbase = blockIdx.x * JCHUNK;
    if (t < TI * NH) {
        zinv_s[t] = g_Zinv[i0 * NH + t];
        src_s[t]  = g_srcT[i0 * NH + t];
    }
    int tc = t & 63, tr = t >> 6;
    int hgrp = tc >> 3;
    float acc[8][8];
#pragma unroll
    for (int a = 0; a < 8; a++)
#pragma unroll
        for (int b = 0; b < 8; b++) acc[a][b] = 0.f;

    for (int jt = 0; jt < JCHUNK / TJ; jt++) {
        int j0 = jbase + jt * TJ;
        __syncthreads();
        // load Wh tile [TJ][CC]
#pragma unroll
        for (int q = 0; q < 8; q++) {
            int idx = q * 512 + t;          // float4 index 0..4095
            int jj = idx >> 7;
            int c4 = (idx & 127) << 2;
            *(float4*)&wh_s[jj * CC + c4] =
                *(const float4*)&g_Wh[(size_t)(j0 + jj) * CC + c4];
        }
        if (t < NH * TJ) {
            int h = t >> 5, k = t & 31;
            dst_s[h * TJ + k] = g_dstT[(size_t)(j0 + k) * NH + h];
        }
        __syncthreads();
        // compute normalized p into smem + write avg_attention
#pragma unroll
        for (int m = 0; m < 4; m++) {
            int pi = (m << 9) + t;
            int r = pi >> 5;
            int k = pi & 31;
            int a = adj[(size_t)(i0 + r) * Nn + j0 + k];
            float4 s0 = *(const float4*)&src_s[r * NH];
            float4 s1 = *(const float4*)&src_s[r * NH + 4];
            float4 z0 = *(const float4*)&zinv_s[r * NH];
            float4 z1 = *(const float4*)&zinv_s[r * NH + 4];
            float sv[8] = {s0.x, s0.y, s0.z, s0.w, s1.x, s1.y, s1.z, s1.w};
            float zv[8] = {z0.x, z0.y, z0.z, z0.w, z1.x, z1.y, z1.z, z1.w};
            float* pbase = &p_s[k * KS + r];
            float sumh = 0.f;
            if (a > 0) {
#pragma unroll
                for (int h = 0; h < NH; h++) {
                    float pv = __expf(lrelu(sv[h] + dst_s[h * TJ + k])) * zv[h];
                    pbase[h * 68] = pv;
                    sumh += pv;
                }
            } else {
#pragma unroll
                for (int h = 0; h < NH; h++) pbase[h * 68] = 0.f;
            }
            avg[(size_t)(i0 + r) * Nn + j0 + k] = sumh * 0.125f;
        }
        __syncthreads();
        // 8x8 register-tile GEMM: acc += P^T chunk * Wh chunk
#pragma unroll 4
        for (int k = 0; k < TJ; k++) {
            const float* pp = &p_s[k * KS + hgrp * 68 + tr * 8];
            float a0[8];
#pragma unroll
            for (int r = 0; r < 8; r++) a0[r] = pp[r];
            const float* wp = &wh_s[k * CC + tc * 8];
            float4 b4a = *(const float4*)wp;
            float4 b4b = *(const float4*)(wp + 4);
            float b0[8] = {b4a.x, b4a.y, b4a.z, b4a.w, b4b.x, b4b.y, b4b.z, b4b.w};
#pragma unroll
            for (int r = 0; r < 8; r++)
#pragma unroll
                for (int c = 0; c < 8; c++) acc[r][c] += a0[r] * b0[c];
        }
    }
    float* dst = g_hp[blockIdx.x];
#pragma unroll
    for (int r = 0; r < 8; r++) {
        int grow = i0 + tr * 8 + r;
        float4 v0 = make_float4(acc[r][0], acc[r][1], acc[r][2], acc[r][3]);
        float4 v1 = make_float4(acc[r][4], acc[r][5], acc[r][6], acc[r][7]);
        *(float4*)&dst[(size_t)grow * CC + tc * 8] = v0;
        *(float4*)&dst[(size_t)grow * CC + tc * 8 + 4] = v1;
    }
}

// ====== K4: elu + Wh2 = x2 @ W_out + src2/dst2 ======
__global__ void __launch_bounds__(128) k4_out(const float* __restrict__ Wout,
                                              const float* __restrict__ aos,
                                              const float* __restrict__ aod) {
    int w = threadIdx.x >> 5, lane = threadIdx.x & 31;
    int row = blockIdx.x * 4 + w;
    const float* h0 = g_hp[0] + (size_t)row * CC;
    const float* h1 = g_hp[1] + (size_t)row * CC;
    const float* h2 = g_hp[2] + (size_t)row * CC;
    float acc[NC];
#pragma unroll
    for (int c = 0; c < NC; c++) acc[c] = 0.f;
#pragma unroll 4
    for (int m = 0; m < FIN / 32; m++) {
        int k = m * 32 + lane;
        float v = h0[k] + h1[k] + h2[k];
        v = v > 0.f ? v : (__expf(v) - 1.f);   // elu
        const float4* wp = (const float4*)(Wout + (size_t)k * NC);
        float4 w0 = wp[0], w1 = wp[1], w2 = wp[2], w3 = wp[3];
        acc[0] += v * w0.x; acc[1] += v * w0.y; acc[2] += v * w0.z; acc[3] += v * w0.w;
        acc[4] += v * w1.x; acc[5] += v * w1.y; acc[6] += v * w1.z; acc[7] += v * w1.w;
        acc[8] += v * w2.x; acc[9] += v * w2.y; acc[10] += v * w2.z; acc[11] += v * w2.w;
        acc[12] += v * w3.x; acc[13] += v * w3.y; acc[14] += v * w3.z; acc[15] += v * w3.w;
    }
#pragma unroll
    for (int c = 0; c < NC; c++) {
        float v = acc[c];
#pragma unroll
        for (int o = 16; o; o >>= 1) v += __shfl_down_sync(0xffffffffu, v, o);
        acc[c] = v;
    }
    if (!lane) {
        float s = 0.f, d = 0.f;
#pragma unroll
        for (int c = 0; c < NC; c++) {
            g_Wh2[(size_t)row * NC + c] = acc[c];
            s += acc[c] * aos[c];
            d += acc[c] * aod[c];
        }
        g_s2[row] = s;
        g_d2[row] = d;
    }
}

// ====== K5: output attention + log_softmax ======
__global__ void __launch_bounds__(256) k5_final(const int* __restrict__ adj,
                                                float* __restrict__ out) {
    extern __shared__ float sm5[];
    float* p   = sm5;                 // TI5*Nn
    float* w2s = p + TI5 * Nn;        // 256*17
    float* red = w2s + 256 * 17;      // 64
    int i0 = blockIdx.x * TI5;
    int t = threadIdx.x, lane = t & 31, w = t >> 5;

    float zs[TI5], s2v[TI5];
#pragma unroll
    for (int i = 0; i < TI5; i++) { zs[i] = 0.f; s2v[i] = g_s2[i0 + i]; }
    for (int j = t; j < Nn; j += 256) {
        float dv = g_d2[j];
#pragma unroll
        for (int i = 0; i < TI5; i++) {
            float pv = 0.f;
            if (adj[(size_t)(i0 + i) * Nn + j] > 0)
                pv = __expf(lrelu(s2v[i] + dv));
            p[i * Nn + j] = pv;
            zs[i] += pv;
        }
    }
#pragma unroll
    for (int i = 0; i < TI5; i++) {
        float v = zs[i];
#pragma unroll
        for (int o = 16; o; o >>= 1) v += __shfl_down_sync(0xffffffffu, v, o);
        if (!lane) red[w * TI5 + i] = v;
    }
    __syncthreads();
    float Z = 0.f;                       // warp w handles row w
#pragma unroll
    for (int ww = 0; ww < 8; ww++) Z += red[ww * TI5 + w];
    float zinv = 1.f / Z;

    float acc[NC];
#pragma unroll
    for (int c = 0; c < NC; c++) acc[c] = 0.f;
    for (int j0 = 0; j0 < Nn; j0 += 256) {
        __syncthreads();
        {
            const float4* gw = (const float4*)&g_Wh2[(size_t)(j0 + t) * NC];
            float4 v0 = gw[0], v1 = gw[1], v2 = gw[2], v3 = gw[3];
            float* ds = &w2s[t * 17];
            ds[0] = v0.x; ds[1] = v0.y; ds[2] = v0.z; ds[3] = v0.w;
            ds[4] = v1.x; ds[5] = v1.y; ds[6] = v1.z; ds[7] = v1.w;
            ds[8] = v2.x; ds[9] = v2.y; ds[10] = v2.z; ds[11] = v2.w;
            ds[12] = v3.x; ds[13] = v3.y; ds[14] = v3.z; ds[15] = v3.w;
        }
        __syncthreads();
#pragma unroll
        for (int jj0 = 0; jj0 < 256; jj0 += 32) {
            int jj = jj0 + lane;
            float pv = p[w * Nn + j0 + jj];
            const float* wr = &w2s[jj * 17];
#pragma unroll
            for (int c = 0; c < NC; c++) acc[c] += pv * wr[c];
        }
    }
#pragma unroll
    for (int c = 0; c < NC; c++) {
        float v = acc[c];
#pragma unroll
        for (int o = 16; o; o >>= 1) v += __shfl_down_sync(0xffffffffu, v, o);
        acc[c] = v;
    }
    if (!lane) {
        float ho[NC];
        float mx = -1e30f;
#pragma unroll
        for (int c = 0; c < NC; c++) { ho[c] = acc[c] * zinv; mx = fmaxf(mx, ho[c]); }
        float se = 0.f;
#pragma unroll
        for (int c = 0; c < NC; c++) se += __expf(ho[c] - mx);
        float lse = mx + __logf(se);
#pragma unroll
        for (int c = 0; c < NC; c++) out[(size_t)(i0 + w) * NC + c] = ho[c] - lse;
    }
}

// =======================================================================
extern "C" void kernel_launch(void* const* d_in, const int* in_sizes, int n_in,
                              void* d_out, int out_size) {
    const float* x     = (const float*)d_in[0];
    const int*   adj   = (const int*)d_in[1];
    const float* Whd   = (const float*)d_in[2];
    const float* a_src = (const float*)d_in[3];
    const float* a_dst = (const float*)d_in[4];
    const float* Wout  = (const float*)d_in[5];
    const float* aos   = (const float*)d_in[6];
    const float* aod   = (const float*)d_in[7];
    float* out = (float*)d_out;
    float* avg = out + (size_t)Nn * NC;   // (logp, avg_attention) concatenated

    const int SMEM3 = (TJ * CC + TJ * KS + NH * TJ + TI * NH + TI * NH) * 4;
    const int SMEM5 = (TI5 * Nn + 256 * 17 + 64) * 4;
    cudaFuncSetAttribute(k3_att, cudaFuncAttributeMaxDynamicSharedMemorySize, SMEM3);
    cudaFuncSetAttribute(k5_final, cudaFuncAttributeMaxDynamicSharedMemorySize, SMEM5);

    k1_gemm<<<dim3(CC / 64, Nn / 64), 256>>>(x, Whd);
    k_srcdst<<<Nn, 256>>>(a_src, a_dst);
    k2_z<<<Nn, 256>>>(adj);
    k3_att<<<dim3(JSPLIT, Nn / TI), 512, SMEM3>>>(adj, avg);
    k4_out<<<Nn / 4, 128>>>(Wout, aos, aod);
    k5_final<<<Nn / TI5, 256, SMEM5>>>(adj, out);
}

// round 2
// speedup vs baseline: 1.1814x; 1.1814x over previous
#include <cuda_runtime.h>
#include <cstdint>

#define Nn   3072
#define FIN  512
#define FH   64
#define NH   8
#define CC   512     // NH*FH
#define NC   16
#define LRA  0.2f
#define JSPLIT 3
#define JCHUNK 1024  // Nn/JSPLIT
#define TI   64
#define TJ   32
#define KSP  516     // p_s per-j stride (8*64 + 4; /4=129 odd -> conflict-free STS.128)
#define HS   64      // p_s per-head stride
#define TI5  8

typedef unsigned long long u64;

// ---- static device scratch (no allocations allowed) ----
__device__ float g_Wh[Nn * CC];          // [n][h*64+o]
__device__ float g_srcT[Nn * NH];        // [n][h]
__device__ float g_dstT[Nn * NH];        // [n][h]
__device__ float g_Zinv[Nn * NH];        // [n][h]
__device__ float g_hp[JSPLIT][Nn * CC];  // partial h' per j-split
__device__ float g_Wh2[Nn * NC];
__device__ float g_s2[Nn];
__device__ float g_d2[Nn];

__device__ __forceinline__ float lrelu(float x) { return fmaxf(x, LRA * x); }

// packed fp32x2 helpers (FFMA2 — 2 MACs/instr, ptxas never auto-emits)
__device__ __forceinline__ void ffma2(u64& d, u64 a, u64 b) {
    asm("fma.rn.f32x2 %0, %1, %2, %0;" : "+l"(d) : "l"(a), "l"(b));
}
__device__ __forceinline__ u64 dup2(float x) {
    u64 r;
    asm("mov.b64 %0, {%1, %1};" : "=l"(r) : "f"(x));
    return r;
}
__device__ __forceinline__ float2 unpk(u64 v) {
    float2 r;
    asm("mov.b64 {%0, %1}, %2;" : "=f"(r.x), "=f"(r.y) : "l"(v));
    return r;
}

// ================= K1: Wh = x @ W (64x64 tile SGEMM, f32x2) =================
__global__ void __launch_bounds__(256) k1_gemm(const float* __restrict__ x,
                                               const float* __restrict__ W) {
    __shared__ float As[16][64];   // [k][row]
    __shared__ float Bs[16][64];   // [k][col]
    int tx = threadIdx.x & 15, ty = threadIdx.x >> 4;
    int row0 = blockIdx.y * 64, col0 = blockIdx.x * 64;
    int h = col0 >> 6;                          // 64-wide col tile = one head
    const float* Wb = W + (size_t)h * FIN * FH; // [FIN][64]
    u64 acc[2][4];
#pragma unroll
    for (int i = 0; i < 2; i++)
#pragma unroll
        for (int j = 0; j < 4; j++) acc[i][j] = 0ull;

    for (int k0 = 0; k0 < FIN; k0 += 16) {
        {
            int t = threadIdx.x;
            int r = t >> 2;
            int c4 = (t & 3) << 2;
            float4 v = *(const float4*)&x[(size_t)(row0 + r) * FIN + k0 + c4];
            As[c4 + 0][r] = v.x; As[c4 + 1][r] = v.y;
            As[c4 + 2][r] = v.z; As[c4 + 3][r] = v.w;
        }
        {
            int t = threadIdx.x;
            int r = t >> 4;
            int c4 = (t & 15) << 2;
            float4 v = *(const float4*)&Wb[(size_t)(k0 + r) * FH + c4];
            *(float4*)&Bs[r][c4] = v;
        }
        __syncthreads();
#pragma unroll
        for (int k = 0; k < 16; k++) {
            ulonglong2 ap = *(const ulonglong2*)&As[k][ty * 4];   // rows paired
            float4 b4 = *(const float4*)&Bs[k][tx * 4];
            u64 bd[4] = {dup2(b4.x), dup2(b4.y), dup2(b4.z), dup2(b4.w)};
#pragma unroll
            for (int c = 0; c < 4; c++) {
                ffma2(acc[0][c], ap.x, bd[c]);
                ffma2(acc[1][c], ap.y, bd[c]);
            }
        }
        __syncthreads();
    }
#pragma unroll
    for (int rp = 0; rp < 2; rp++) {
        float2 c0 = unpk(acc[rp][0]), c1 = unpk(acc[rp][1]);
        float2 c2 = unpk(acc[rp][2]), c3 = unpk(acc[rp][3]);
        int r = row0 + ty * 4 + rp * 2;
        *(float4*)&g_Wh[(size_t)r * CC + col0 + tx * 4] =
            make_float4(c0.x, c1.x, c2.x, c3.x);
        *(float4*)&g_Wh[(size_t)(r + 1) * CC + col0 + tx * 4] =
            make_float4(c0.y, c1.y, c2.y, c3.y);
    }
}

// ================= K1b: src/dst projections =================
__global__ void __launch_bounds__(256) k_srcdst(const float* __restrict__ a_src,
                                                const float* __restrict__ a_dst) {
    int n = blockIdx.x;
    int h = threadIdx.x >> 5, lane = threadIdx.x & 31;
    const float* wh = g_Wh + (size_t)n * CC + h * FH;
    float w0 = wh[lane], w1 = wh[lane + 32];
    float s = w0 * a_src[h * FH + lane] + w1 * a_src[h * FH + lane + 32];
    float d = w0 * a_dst[h * FH + lane] + w1 * a_dst[h * FH + lane + 32];
#pragma unroll
    for (int o = 16; o; o >>= 1) {
        s += __shfl_down_sync(0xffffffffu, s, o);
        d += __shfl_down_sync(0xffffffffu, d, o);
    }
    if (!lane) { g_srcT[n * NH + h] = s; g_dstT[n * NH + h] = d; }
}

// ================= K2: softmax denominators Z[h,i] =================
__global__ void __launch_bounds__(256) k2_z(const int* __restrict__ adj) {
    int i = blockIdx.x;
    float sr[NH], sum[NH];
#pragma unroll
    for (int h = 0; h < NH; h++) { sr[h] = g_srcT[i * NH + h]; sum[h] = 0.f; }
    const int* arow = adj + (size_t)i * Nn;
    for (int j = threadIdx.x; j < Nn; j += 256) {
        if (arow[j] > 0) {
            const float4* dp = (const float4*)(g_dstT + (size_t)j * NH);
            float4 d0 = dp[0], d1 = dp[1];
            float dv[8] = {d0.x, d0.y, d0.z, d0.w, d1.x, d1.y, d1.z, d1.w};
#pragma unroll
            for (int h = 0; h < NH; h++) sum[h] += __expf(lrelu(sr[h] + dv[h]));
        }
    }
    __shared__ float red[8][NH];
    int lane = threadIdx.x & 31, w = threadIdx.x >> 5;
#pragma unroll
    for (int h = 0; h < NH; h++) {
        float v = sum[h];
#pragma unroll
        for (int o = 16; o; o >>= 1) v += __shfl_down_sync(0xffffffffu, v, o);
        if (!lane) red[w][h] = v;
    }
    __syncthreads();
    if (threadIdx.x < NH) {
        float v = 0.f;
#pragma unroll
        for (int ww = 0; ww < 8; ww++) v += red[ww][threadIdx.x];
        g_Zinv[i * NH + threadIdx.x] = 1.f / v;
    }
}

// ====== K3: fused attention p-gen + avg_attention write + (att @ Wh) ======
// p_s layout: [j-in-tile][head][row]  stride KSP=516 per j, HS=64 per head.
// GEMM thread tile: 16 rows x 4 cols (row-pairs packed for FFMA2).
__global__ void __launch_bounds__(512) k3_att(const int* __restrict__ adj,
                                              float* __restrict__ avg) {
    extern __shared__ float sm[];
    float* wh_s   = sm;                       // TJ*CC   = 16384
    float* p_s    = sm + TJ * CC;             // TJ*KSP  = 16512
    float* dst_s  = p_s + TJ * KSP;           // NH*TJ   = 256  [h][j]
    float* src_s  = dst_s + NH * TJ;          // TI*NH   = 512  [r][h]
    float* zinv_s = src_s + TI * NH;          // TI*NH   = 512

    int t = threadIdx.x;
    int i0 = blockIdx.y * TI;
    int jbase = blockIdx.x * JCHUNK;
    src_s[t]  = g_srcT[i0 * NH + t];
    zinv_s[t] = g_Zinv[i0 * NH + t];

    // GEMM ids
    int tc = t & 127, tr = t >> 7;
    int col0 = tc * 4;
    int hg   = tc >> 4;          // head of this column group
    int r0g  = tr * 16;
    // p-gen ids
    int lane = t & 31, w = t >> 5;
    int r0p = w * 4;

    u64 acc[8][4];
#pragma unroll
    for (int a = 0; a < 8; a++)
#pragma unroll
        for (int b = 0; b < 4; b++) acc[a][b] = 0ull;

    for (int jt = 0; jt < JCHUNK / TJ; jt++) {
        int j0 = jbase + jt * TJ;
        __syncthreads();
        // load Wh tile [TJ][CC]
#pragma unroll
        for (int q = 0; q < 8; q++) {
            int idx = q * 512 + t;
            int jj = idx >> 7;
            int c4 = (idx & 127) << 2;
            *(float4*)&wh_s[jj * CC + c4] =
                *(const float4*)&g_Wh[(size_t)(j0 + jj) * CC + c4];
        }
        if (t < NH * TJ) {
            int h = t >> 5, k = t & 31;
            dst_s[h * TJ + k] = g_dstT[(size_t)(j0 + k) * NH + h];
        }
        __syncthreads();
        // p-gen: warp w owns rows r0p..r0p+3, all heads; lane = j-in-tile
        {
            float msk[4], sumv[4];
#pragma unroll
            for (int rr = 0; rr < 4; rr++) {
                msk[rr] = adj[(size_t)(i0 + r0p + rr) * Nn + j0 + lane] > 0 ? 1.f : 0.f;
                sumv[rr] = 0.f;
            }
#pragma unroll
            for (int m = 0; m < 4; m++) {
                int h0 = m * 2;
                float d0 = dst_s[h0 * TJ + lane];
                float d1 = dst_s[(h0 + 1) * TJ + lane];
                float4 v0, v1;
                float* pv0 = &v0.x;
                float* pv1 = &v1.x;
#pragma unroll
                for (int rr = 0; rr < 4; rr++) {
                    int r = r0p + rr;
                    float p0 = __expf(lrelu(src_s[r * NH + h0] + d0)) *
                               zinv_s[r * NH + h0] * msk[rr];
                    float p1 = __expf(lrelu(src_s[r * NH + h0 + 1] + d1)) *
                               zinv_s[r * NH + h0 + 1] * msk[rr];
                    pv0[rr] = p0; pv1[rr] = p1;
                    sumv[rr] += p0 + p1;
                }
                *(float4*)&p_s[lane * KSP + h0 * HS + r0p] = v0;
                *(float4*)&p_s[lane * KSP + (h0 + 1) * HS + r0p] = v1;
            }
#pragma unroll
            for (int rr = 0; rr < 4; rr++)
                avg[(size_t)(i0 + r0p + rr) * Nn + j0 + lane] = sumv[rr] * 0.125f;
        }
        __syncthreads();
        // GEMM: acc[16 rows x 4 cols] += p^T * wh   (row-pairs packed)
#pragma unroll 4
        for (int k = 0; k < TJ; k++) {
            const float* pb = &p_s[k * KSP + hg * HS + r0g];
            ulonglong2 a01 = *(const ulonglong2*)(pb);
            ulonglong2 a23 = *(const ulonglong2*)(pb + 4);
            ulonglong2 a45 = *(const ulonglong2*)(pb + 8);
            ulonglong2 a67 = *(const ulonglong2*)(pb + 12);
            float4 b4 = *(const float4*)&wh_s[k * CC + col0];
            u64 bd[4] = {dup2(b4.x), dup2(b4.y), dup2(b4.z), dup2(b4.w)};
#pragma unroll
            for (int c = 0; c < 4; c++) {
                ffma2(acc[0][c], a01.x, bd[c]);
                ffma2(acc[1][c], a01.y, bd[c]);
                ffma2(acc[2][c], a23.x, bd[c]);
                ffma2(acc[3][c], a23.y, bd[c]);
                ffma2(acc[4][c], a45.x, bd[c]);
                ffma2(acc[5][c], a45.y, bd[c]);
                ffma2(acc[6][c], a67.x, bd[c]);
                ffma2(acc[7][c], a67.y, bd[c]);
            }
        }
    }
    float* dst = g_hp[blockIdx.x];
#pragma unroll
    for (int rp = 0; rp < 8; rp++) {
        float2 c0 = unpk(acc[rp][0]), c1 = unpk(acc[rp][1]);
        float2 c2 = unpk(acc[rp][2]), c3 = unpk(acc[rp][3]);
        int r = i0 + r0g + rp * 2;
        *(float4*)&dst[(size_t)r * CC + col0] = make_float4(c0.x, c1.x, c2.x, c3.x);
        *(float4*)&dst[(size_t)(r + 1) * CC + col0] = make_float4(c0.y, c1.y, c2.y, c3.y);
    }
}

// ====== K4: elu + Wh2 = x2 @ W_out + src2/dst2 ======
__global__ void __launch_bounds__(128) k4_out(const float* __restrict__ Wout,
                                              const float* __restrict__ aos,
                                              const float* __restrict__ aod) {
    int w = threadIdx.x >> 5, lane = threadIdx.x & 31;
    int row = blockIdx.x * 4 + w;
    const float* h0 = g_hp[0] + (size_t)row * CC;
    const float* h1 = g_hp[1] + (size_t)row * CC;
    const float* h2 = g_hp[2] + (size_t)row * CC;
    float acc[NC];
#pragma unroll
    for (int c = 0; c < NC; c++) acc[c] = 0.f;
#pragma unroll 4
    for (int m = 0; m < FIN / 32; m++) {
        int k = m * 32 + lane;
        float v = h0[k] + h1[k] + h2[k];
        v = v > 0.f ? v : (__expf(v) - 1.f);   // elu
        const float4* wp = (const float4*)(Wout + (size_t)k * NC);
        float4 w0 = wp[0], w1 = wp[1], w2 = wp[2], w3 = wp[3];
        acc[0] += v * w0.x; acc[1] += v * w0.y; acc[2] += v * w0.z; acc[3] += v * w0.w;
        acc[4] += v * w1.x; acc[5] += v * w1.y; acc[6] += v * w1.z; acc[7] += v * w1.w;
        acc[8] += v * w2.x; acc[9] += v * w2.y; acc[10] += v * w2.z; acc[11] += v * w2.w;
        acc[12] += v * w3.x; acc[13] += v * w3.y; acc[14] += v * w3.z; acc[15] += v * w3.w;
    }
#pragma unroll
    for (int c = 0; c < NC; c++) {
        float v = acc[c];
#pragma unroll
        for (int o = 16; o; o >>= 1) v += __shfl_down_sync(0xffffffffu, v, o);
        acc[c] = v;
    }
    if (!lane) {
        float s = 0.f, d = 0.f;
#pragma unroll
        for (int c = 0; c < NC; c++) {
            g_Wh2[(size_t)row * NC + c] = acc[c];
            s += acc[c] * aos[c];
            d += acc[c] * aod[c];
        }
        g_s2[row] = s;
        g_d2[row] = d;
    }
}

// ====== K5: output attention + log_softmax ======
__global__ void __launch_bounds__(256) k5_final(const int* __restrict__ adj,
                                                float* __restrict__ out) {
    extern __shared__ float sm5[];
    float* p   = sm5;                 // TI5*Nn
    float* w2s = p + TI5 * Nn;        // 256*17
    float* red = w2s + 256 * 17;      // 64
    int i0 = blockIdx.x * TI5;
    int t = threadIdx.x, lane = t & 31, w = t >> 5;

    float zs[TI5], s2v[TI5];
#pragma unroll
    for (int i = 0; i < TI5; i++) { zs[i] = 0.f; s2v[i] = g_s2[i0 + i]; }
    for (int j = t; j < Nn; j += 256) {
        float dv = g_d2[j];
#pragma unroll
        for (int i = 0; i < TI5; i++) {
            float pv = 0.f;
            if (adj[(size_t)(i0 + i) * Nn + j] > 0)
                pv = __expf(lrelu(s2v[i] + dv));
            p[i * Nn + j] = pv;
            zs[i] += pv;
        }
    }
#pragma unroll
    for (int i = 0; i < TI5; i++) {
        float v = zs[i];
#pragma unroll
        for (int o = 16; o; o >>= 1) v += __shfl_down_sync(0xffffffffu, v, o);
        if (!lane) red[w * TI5 + i] = v;
    }
    __syncthreads();
    float Z = 0.f;                       // warp w handles row w
#pragma unroll
    for (int ww = 0; ww < 8; ww++) Z += red[ww * TI5 + w];
    float zinv = 1.f / Z;

    float acc[NC];
#pragma unroll
    for (int c = 0; c < NC; c++) acc[c] = 0.f;
    for (int j0 = 0; j0 < Nn; j0 += 256) {
        __syncthreads();
        {
            const float4* gw = (const float4*)&g_Wh2[(size_t)(j0 + t) * NC];
            float4 v0 = gw[0], v1 = gw[1], v2 = gw[2], v3 = gw[3];
            float* ds = &w2s[t * 17];
            ds[0] = v0.x; ds[1] = v0.y; ds[2] = v0.z; ds[3] = v0.w;
            ds[4] = v1.x; ds[5] = v1.y; ds[6] = v1.z; ds[7] = v1.w;
            ds[8] = v2.x; ds[9] = v2.y; ds[10] = v2.z; ds[11] = v2.w;
            ds[12] = v3.x; ds[13] = v3.y; ds[14] = v3.z; ds[15] = v3.w;
        }
        __syncthreads();
#pragma unroll
        for (int jj0 = 0; jj0 < 256; jj0 += 32) {
            int jj = jj0 + lane;
            float pv = p[w * Nn + j0 + jj];
            const float* wr = &w2s[jj * 17];
#pragma unroll
            for (int c = 0; c < NC; c++) acc[c] += pv * wr[c];
        }
    }
#pragma unroll
    for (int c = 0; c < NC; c++) {
        float v = acc[c];
#pragma unroll
        for (int o = 16; o; o >>= 1) v += __shfl_down_sync(0xffffffffu, v, o);
        acc[c] = v;
    }
    if (!lane) {
        float ho[NC];
        float mx = -1e30f;
#pragma unroll
        for (int c = 0; c < NC; c++) { ho[c] = acc[c] * zinv; mx = fmaxf(mx, ho[c]); }
        float se = 0.f;
#pragma unroll
        for (int c = 0; c < NC; c++) se += __expf(ho[c] - mx);
        float lse = mx + __logf(se);
#pragma unroll
        for (int c = 0; c < NC; c++) out[(size_t)(i0 + w) * NC + c] = ho[c] - lse;
    }
}

// =======================================================================
extern "C" void kernel_launch(void* const* d_in, const int* in_sizes, int n_in,
                              void* d_out, int out_size) {
    const float* x     = (const float*)d_in[0];
    const int*   adj   = (const int*)d_in[1];
    const float* Whd   = (const float*)d_in[2];
    const float* a_src = (const float*)d_in[3];
    const float* a_dst = (const float*)d_in[4];
    const float* Wout  = (const float*)d_in[5];
    const float* aos   = (const float*)d_in[6];
    const float* aod   = (const float*)d_in[7];
    float* out = (float*)d_out;
    float* avg = out + (size_t)Nn * NC;   // (logp, avg_attention) concatenated

    const int SMEM3 = (TJ * CC + TJ * KSP + NH * TJ + TI * NH + TI * NH) * 4;
    const int SMEM5 = (TI5 * Nn + 256 * 17 + 64) * 4;
    cudaFuncSetAttribute(k3_att, cudaFuncAttributeMaxDynamicSharedMemorySize, SMEM3);
    cudaFuncSetAttribute(k5_final, cudaFuncAttributeMaxDynamicSharedMemorySize, SMEM5);

    k1_gemm<<<dim3(CC / 64, Nn / 64), 256>>>(x, Whd);
    k_srcdst<<<Nn, 256>>>(a_src, a_dst);
    k2_z<<<Nn, 256>>>(adj);
    k3_att<<<dim3(JSPLIT, Nn / TI), 512, SMEM3>>>(adj, avg);
    k4_out<<<Nn / 4, 128>>>(Wout, aos, aod);
    k5_final<<<Nn / TI5, 256, SMEM5>>>(adj, out);
}